// round 1
// baseline (speedup 1.0000x reference)
#include <cuda_runtime.h>
#include <math.h>

#define B_ 8
#define N_ 8192
#define K_ 32
#define D_ 64

// ---------------- shared memory layout (in floats) ----------------
#define OFF_W0T   0            // [129][64] transposed W0 (i-major)
#define OFF_W1T   8256         // [64][64]
#define OFF_W2T   12352        // [64][64]
#define OFF_B0    16448        // 64
#define OFF_B1    16512        // 64
#define OFF_B2    16576        // 64
#define OFF_SELF  16640        // 4 nodes x 64  (emb*mask)
#define OFF_SELFC 16896        // 4 nodes x 64  (b0 + self-part of layer0)
#define OFF_DIST  17152        // 128
#define OFF_VALID 17280        // 128
#define OFF_IDX   17408        // 128 ints
#define OFF_MASKF 17536        // 4
#define OFF_FACT  17540        // 4 (mask / n_valid)
#define OFF_SRC   17552        // 128 rows x 68 (gathered src; reused as H1)
#define OFF_H0    26256        // 128 rows x 68 (layer0 out; reused as partials)
#define SMEM_FLOATS 34960      // 139840 bytes

// ---------------- device scratch (no allocation allowed) ----------------
__device__ float g_upd[B_ * N_ * D_];
__device__ float g_sum[B_][D_];
__device__ float g_sqs[B_][D_];
__device__ float g_cnt[B_];

__device__ __forceinline__ float gelu_f(float x) {
    return 0.5f * x * (1.0f + erff(x * 0.7071067811865475f));
}

// acc[r][j] += sum_i  in[ebase+r][i] * Wt[i][d0+j]   (64-dim inner)
__device__ __forceinline__ void mm16(const float* __restrict__ sIn,
                                     const float* __restrict__ sWt,
                                     int ebase, int d0, float acc[4][4]) {
#pragma unroll 4
    for (int i = 0; i < 64; i += 4) {
        float4 w0 = *reinterpret_cast<const float4*>(sWt + (i + 0) * 64 + d0);
        float4 w1 = *reinterpret_cast<const float4*>(sWt + (i + 1) * 64 + d0);
        float4 w2 = *reinterpret_cast<const float4*>(sWt + (i + 2) * 64 + d0);
        float4 w3 = *reinterpret_cast<const float4*>(sWt + (i + 3) * 64 + d0);
#pragma unroll
        for (int r = 0; r < 4; r++) {
            float4 f = *reinterpret_cast<const float4*>(sIn + (ebase + r) * 68 + i);
            acc[r][0] = fmaf(f.x, w0.x, acc[r][0]);
            acc[r][0] = fmaf(f.y, w1.x, acc[r][0]);
            acc[r][0] = fmaf(f.z, w2.x, acc[r][0]);
            acc[r][0] = fmaf(f.w, w3.x, acc[r][0]);
            acc[r][1] = fmaf(f.x, w0.y, acc[r][1]);
            acc[r][1] = fmaf(f.y, w1.y, acc[r][1]);
            acc[r][1] = fmaf(f.z, w2.y, acc[r][1]);
            acc[r][1] = fmaf(f.w, w3.y, acc[r][1]);
            acc[r][2] = fmaf(f.x, w0.z, acc[r][2]);
            acc[r][2] = fmaf(f.y, w1.z, acc[r][2]);
            acc[r][2] = fmaf(f.z, w2.z, acc[r][2]);
            acc[r][2] = fmaf(f.w, w3.z, acc[r][2]);
            acc[r][3] = fmaf(f.x, w0.w, acc[r][3]);
            acc[r][3] = fmaf(f.y, w1.w, acc[r][3]);
            acc[r][3] = fmaf(f.z, w2.w, acc[r][3]);
            acc[r][3] = fmaf(f.w, w3.w, acc[r][3]);
        }
    }
}

__global__ void __launch_bounds__(512, 1)
mpnn_msg_kernel(const float* __restrict__ emb,
                const float* __restrict__ dists,
                const int*   __restrict__ eidx,
                const float* __restrict__ mask,
                const float* __restrict__ W0, const float* __restrict__ b0,
                const float* __restrict__ W1, const float* __restrict__ b1,
                const float* __restrict__ W2, const float* __restrict__ b2)
{
    extern __shared__ float sm[];
    const int tid = threadIdx.x;

    // load weights transposed (one-time per block)
    for (int p = tid; p < 129 * 64; p += 512) {
        int i = p >> 6, d = p & 63;
        sm[OFF_W0T + p] = W0[d * 129 + i];
    }
    for (int p = tid; p < 64 * 64; p += 512) {
        int i = p >> 6, d = p & 63;
        sm[OFF_W1T + p] = W1[d * 64 + i];
        sm[OFF_W2T + p] = W2[d * 64 + i];
    }
    if (tid < 64) {
        sm[OFF_B0 + tid] = b0[tid];
        sm[OFF_B1 + tid] = b1[tid];
        sm[OFF_B2 + tid] = b2[tid];
    }
    __syncthreads();

    int* sIdx = reinterpret_cast<int*>(sm + OFF_IDX);
    const int d0    = (tid & 15) << 2;   // output channel base (4 contiguous)
    const int g     = tid >> 4;          // edge group 0..31
    const int ebase = g << 2;            // 4 edges per thread
    const int snode = g >> 3;            // node slot 0..3

    const int totalIter = (B_ * N_) >> 2;
    for (int iter = blockIdx.x; iter < totalIter; iter += gridDim.x) {
        const int bn0 = iter << 2;
        const int b   = bn0 >> 13;          // /N_
        const int n0  = bn0 & (N_ - 1);

        // ---- phase 1: per-edge meta + self embedding ----
        if (tid < 128) {
            int s = tid >> 5;
            int off = (b * N_ + n0 + s) * K_ + (tid & 31);
            int idx = eidx[off];
            sm[OFF_VALID + tid] = (idx != -1) ? 1.0f : 0.0f;
            sIdx[tid] = (idx == -1) ? 0 : idx;
            sm[OFF_DIST + tid] = dists[off];
        } else if (tid < 384) {
            int t = tid - 128;
            int s = t >> 6, c = t & 63;
            int row = b * N_ + n0 + s;
            sm[OFF_SELF + t] = emb[row * 64 + c] * mask[row];
        } else if (tid < 388) {
            sm[OFF_MASKF + tid - 384] = mask[b * N_ + n0 + (tid - 384)];
        }
        __syncthreads();

        // ---- phase 2: gather src feats + self contribution + n_valid ----
#pragma unroll
        for (int q = 0; q < 4; q++) {
            int pos = tid + q * 512;         // 0..2047
            int eb = pos >> 4, c4 = pos & 15;
            int row = b * N_ + sIdx[eb];
            float m = mask[row];
            float4 v = reinterpret_cast<const float4*>(emb)[row * 16 + c4];
            v.x *= m; v.y *= m; v.z *= m; v.w *= m;
            *reinterpret_cast<float4*>(sm + OFF_SRC + eb * 68 + c4 * 4) = v;
        }
        if (tid < 256) {
            int s = tid >> 6, d = tid & 63;
            float a = sm[OFF_B0 + d];
            const float* sp = sm + OFF_SELF + s * 64;
            const float* wp = sm + OFF_W0T + 64 * 64 + d;
#pragma unroll 8
            for (int i = 0; i < 64; i++) a = fmaf(sp[i], wp[i * 64], a);
            sm[OFF_SELFC + tid] = a;
        } else if (tid < 260) {
            int s = tid - 256;
            float c = 0.0f;
            for (int e = 0; e < 32; e++) c += sm[OFF_VALID + s * 32 + e];
            if (c == 0.0f) c = 1.0f;
            sm[OFF_FACT + s] = sm[OFF_MASKF + s] / c;
        }
        __syncthreads();

        // ---- layer 0: src(64) part + dist, self part prefolded ----
        float acc[4][4];
        {
            float w128[4];
#pragma unroll
            for (int j = 0; j < 4; j++) w128[j] = sm[OFF_W0T + 128 * 64 + d0 + j];
#pragma unroll
            for (int r = 0; r < 4; r++) {
                float dd = sm[OFF_DIST + ebase + r];
#pragma unroll
                for (int j = 0; j < 4; j++)
                    acc[r][j] = fmaf(dd, w128[j], sm[OFF_SELFC + snode * 64 + d0 + j]);
            }
            mm16(sm + OFF_SRC, sm + OFF_W0T, ebase, d0, acc);
#pragma unroll
            for (int r = 0; r < 4; r++) {
                float4 h;
                h.x = gelu_f(acc[r][0]);
                h.y = gelu_f(acc[r][1]);
                h.z = gelu_f(acc[r][2]);
                h.w = gelu_f(acc[r][3]);
                *reinterpret_cast<float4*>(sm + OFF_H0 + (ebase + r) * 68 + d0) = h;
            }
        }
        __syncthreads();

        // ---- layer 1: H0 -> H1 (reuses SRC region) ----
        {
#pragma unroll
            for (int r = 0; r < 4; r++)
#pragma unroll
                for (int j = 0; j < 4; j++) acc[r][j] = sm[OFF_B1 + d0 + j];
            mm16(sm + OFF_H0, sm + OFF_W1T, ebase, d0, acc);
#pragma unroll
            for (int r = 0; r < 4; r++) {
                float4 h;
                h.x = gelu_f(acc[r][0]);
                h.y = gelu_f(acc[r][1]);
                h.z = gelu_f(acc[r][2]);
                h.w = gelu_f(acc[r][3]);
                *reinterpret_cast<float4*>(sm + OFF_SRC + (ebase + r) * 68 + d0) = h;
            }
        }
        __syncthreads();

        // ---- layer 2 + masked per-thread partial aggregation ----
        {
#pragma unroll
            for (int r = 0; r < 4; r++)
#pragma unroll
                for (int j = 0; j < 4; j++) acc[r][j] = sm[OFF_B2 + d0 + j];
            mm16(sm + OFF_SRC, sm + OFF_W2T, ebase, d0, acc);
            float4 p = make_float4(0.f, 0.f, 0.f, 0.f);
#pragma unroll
            for (int r = 0; r < 4; r++) {
                float v = sm[OFF_VALID + ebase + r];
                p.x = fmaf(gelu_f(acc[r][0]), v, p.x);
                p.y = fmaf(gelu_f(acc[r][1]), v, p.y);
                p.z = fmaf(gelu_f(acc[r][2]), v, p.z);
                p.w = fmaf(gelu_f(acc[r][3]), v, p.w);
            }
            // partials: row g, reuses H0 region
            *reinterpret_cast<float4*>(sm + OFF_H0 + g * 68 + d0) = p;
        }
        __syncthreads();

        // ---- final reduce over 8 groups per node, write upd ----
        if (tid < 256) {
            int s = tid >> 6, d = tid & 63;
            float msg = 0.0f;
#pragma unroll
            for (int gg = 0; gg < 8; gg++)
                msg += sm[OFF_H0 + (s * 8 + gg) * 68 + d];
            float upd = sm[OFF_SELF + s * 64 + d] + msg * sm[OFF_FACT + s];
            g_upd[(b * N_ + n0 + s) * 64 + d] = upd;
        }
        __syncthreads();
    }
}

__global__ void zero_stats_kernel() {
    int t = threadIdx.x;
    if (t < B_ * D_) {
        reinterpret_cast<float*>(g_sum)[t] = 0.0f;
        reinterpret_cast<float*>(g_sqs)[t] = 0.0f;
    }
    if (t < B_) g_cnt[t] = 0.0f;
}

__global__ void __launch_bounds__(256)
stats_kernel(const float* __restrict__ mask) {
    __shared__ float sh[512];
    const int b = blockIdx.y;
    const int chunk = blockIdx.x;      // 16 chunks of 512 rows
    const int tid = threadIdx.x;       // 256
    const int d = tid & 63, ro = tid >> 6;
    float s1 = 0.0f, s2 = 0.0f;
    const int base = (b * N_ + chunk * 512) * 64;
    for (int q = 0; q < 128; q++) {
        float v = g_upd[base + (q * 4 + ro) * 64 + d];
        s1 += v;
        s2 = fmaf(v, v, s2);
    }
    sh[tid] = s1;
    sh[256 + tid] = s2;
    __syncthreads();
    if (tid < 64) {
        float a = sh[tid] + sh[tid + 64] + sh[tid + 128] + sh[tid + 192];
        float c = sh[256 + tid] + sh[256 + tid + 64] + sh[256 + tid + 128] + sh[256 + tid + 192];
        atomicAdd(&g_sum[b][tid], a);
        atomicAdd(&g_sqs[b][tid], c);
    }
    __syncthreads();
    // mask count
    float mc = mask[b * N_ + chunk * 512 + tid] + mask[b * N_ + chunk * 512 + 256 + tid];
    sh[tid] = mc;
    __syncthreads();
    for (int st = 128; st >= 1; st >>= 1) {
        if (tid < st) sh[tid] += sh[tid + st];
        __syncthreads();
    }
    if (tid == 0) atomicAdd(&g_cnt[b], sh[0]);
}

__global__ void __launch_bounds__(256)
norm_kernel(const float* __restrict__ mask,
            const float* __restrict__ scale,
            const float* __restrict__ shift,
            float* __restrict__ out) {
    int t = blockIdx.x * 256 + threadIdx.x;
    for (int e = t; e < B_ * N_ * D_; e += gridDim.x * 256) {
        int d  = e & 63;
        int bn = e >> 6;
        int b  = bn >> 13;
        float cnt = g_cnt[b];
        if (cnt == 0.0f) cnt = 1.0f;
        float s1 = g_sum[b][d], s2 = g_sqs[b][d];
        float mean = s1 / cnt;
        float var  = (s2 - 2.0f * mean * s1 + (float)N_ * mean * mean) / cnt;
        float rstd = rsqrtf(var + 1e-5f);
        float v = (g_upd[e] - mean) * rstd;
        out[e] = fmaf(v, scale[d], shift[d]) * mask[bn];
    }
}

extern "C" void kernel_launch(void* const* d_in, const int* in_sizes, int n_in,
                              void* d_out, int out_size) {
    const float* emb   = (const float*)d_in[0];
    const float* dists = (const float*)d_in[1];
    const int*   eidx  = (const int*)d_in[2];
    const float* mask  = (const float*)d_in[3];
    const float* W0 = (const float*)d_in[4];
    const float* b0 = (const float*)d_in[5];
    const float* W1 = (const float*)d_in[6];
    const float* b1 = (const float*)d_in[7];
    const float* W2 = (const float*)d_in[8];
    const float* b2 = (const float*)d_in[9];
    const float* scale = (const float*)d_in[10];
    const float* shift = (const float*)d_in[11];
    float* out = (float*)d_out;

    int smc = 148;
    cudaDeviceGetAttribute(&smc, cudaDevAttrMultiProcessorCount, 0);

    cudaFuncSetAttribute(mpnn_msg_kernel,
                         cudaFuncAttributeMaxDynamicSharedMemorySize,
                         SMEM_FLOATS * 4);

    zero_stats_kernel<<<1, 512>>>();
    mpnn_msg_kernel<<<smc, 512, SMEM_FLOATS * 4>>>(emb, dists, eidx, mask,
                                                   W0, b0, W1, b1, W2, b2);
    stats_kernel<<<dim3(16, 8), 256>>>(mask);
    norm_kernel<<<4096, 256>>>(mask, scale, shift, out);
}